// round 2
// baseline (speedup 1.0000x reference)
#include <cuda_runtime.h>

#define BATCH 4096
#define DIM   4096
#define MARGIN 0.5f

// Scratch (allocation-free rule: __device__ globals).
__device__ float        g_partial[BATCH];
__device__ unsigned int g_count;   // zero-initialized at module load; reset by last block

// ---------------------------------------------------------------------------
// Fused kernel: one CTA per row computes both gathered squared-L2 distances,
// label/margin logic, hinge -> g_partial[i]. The last CTA to finish performs
// a deterministic fixed-order tree reduction of all 4096 partials and resets
// the counter (so every graph replay sees identical state).
// ---------------------------------------------------------------------------
__global__ __launch_bounds__(256, 8)
void triplet_fused_kernel(const float* __restrict__ f,
                          const float* __restrict__ label,
                          const int*   __restrict__ idx1,
                          const int*   __restrict__ idx2,
                          float*       __restrict__ out)
{
    const int i = blockIdx.x;
    const int t = threadIdx.x;

    const int j1 = __ldg(&idx1[i]);
    const int j2 = __ldg(&idx2[i]);

    const float4* __restrict__ a  = (const float4*)(f + (size_t)i  * DIM);
    const float4* __restrict__ b1 = (const float4*)(f + (size_t)j1 * DIM);
    const float4* __restrict__ b2 = (const float4*)(f + (size_t)j2 * DIM);

    float s1 = 0.0f, s2 = 0.0f;

    // DIM/4 = 1024 float4 per row; 256 threads -> 4 iters each
    #pragma unroll
    for (int k = 0; k < 4; k++) {
        const int idx = t + k * 256;
        const float4 av = __ldg(&a[idx]);
        const float4 v1 = __ldg(&b1[idx]);
        const float4 v2 = __ldg(&b2[idx]);
        float d;
        d = av.x - v1.x; s1 = fmaf(d, d, s1);
        d = av.y - v1.y; s1 = fmaf(d, d, s1);
        d = av.z - v1.z; s1 = fmaf(d, d, s1);
        d = av.w - v1.w; s1 = fmaf(d, d, s1);
        d = av.x - v2.x; s2 = fmaf(d, d, s2);
        d = av.y - v2.y; s2 = fmaf(d, d, s2);
        d = av.z - v2.z; s2 = fmaf(d, d, s2);
        d = av.w - v2.w; s2 = fmaf(d, d, s2);
    }

    // warp reduce
    #pragma unroll
    for (int off = 16; off > 0; off >>= 1) {
        s1 += __shfl_down_sync(0xFFFFFFFFu, s1, off);
        s2 += __shfl_down_sync(0xFFFFFFFFu, s2, off);
    }

    __shared__ float sh1[8], sh2[8];
    __shared__ bool  is_last;
    const int wid = t >> 5;
    const int lid = t & 31;
    if (lid == 0) { sh1[wid] = s1; sh2[wid] = s2; }
    __syncthreads();

    if (t == 0) {
        float t1 = 0.0f, t2 = 0.0f;
        #pragma unroll
        for (int w = 0; w < 8; w++) { t1 += sh1[w]; t2 += sh2[w]; }

        const float l  = __ldg(&label[i]);
        const float l1 = __ldg(&label[j1]);
        const float l2 = __ldg(&label[j2]);
        const float d1 = fabsf(l - l1);
        const float d2 = fabsf(l - l2);
        const bool cond = (d1 >= d2);       // true -> idx2 is the near sample

        const float a2n    = cond ? t2 : t1;
        const float a2f    = cond ? t1 : t2;
        const float near_l = cond ? l2 : l1;
        const float far_l  = cond ? l1 : l2;

        const float dn = l - near_l;
        const float df = l - far_l;
        const float alpha = df * df - dn * dn;
        g_partial[i] = fmaxf(a2n - a2f + alpha * MARGIN, 0.0f);

        // make partial visible, then arrive
        __threadfence();
        const unsigned int prev = atomicAdd(&g_count, 1u);
        is_last = (prev == (unsigned int)(gridDim.x - 1));
    }
    __syncthreads();

    // Last CTA: deterministic fixed-order reduction of all partials.
    if (is_last) {
        float s = 0.0f;
        // 4096 / 256 = 16 values per thread, fixed stride order
        #pragma unroll
        for (int k = 0; k < 16; k++)
            s += g_partial[t + k * 256];

        #pragma unroll
        for (int off = 16; off > 0; off >>= 1)
            s += __shfl_down_sync(0xFFFFFFFFu, s, off);

        __shared__ float shr[8];
        if (lid == 0) shr[wid] = s;
        __syncthreads();

        if (t == 0) {
            float tot = 0.0f;
            #pragma unroll
            for (int w = 0; w < 8; w++) tot += shr[w];
            out[0] = tot;
            g_count = 0u;   // reset for next replay (deterministic state)
        }
    }
}

extern "C" void kernel_launch(void* const* d_in, const int* in_sizes, int n_in,
                              void* d_out, int out_size)
{
    const float* f     = (const float*)d_in[0];
    const float* label = (const float*)d_in[1];
    const int*   idx1  = (const int*)d_in[2];
    const int*   idx2  = (const int*)d_in[3];
    float* out = (float*)d_out;

    triplet_fused_kernel<<<BATCH, 256>>>(f, label, idx1, idx2, out);
}